// round 3
// baseline (speedup 1.0000x reference)
#include <cuda_runtime.h>
#include <math.h>

// Problem constants (fixed by the dataset/reference)
#define NNODES 50000
#define EMAX   800000
#define E2MAX  (EMAX + NNODES)
#define HEADS  4

// ---------------- device scratch (no allocations allowed) ----------------
__device__ __align__(16) float g_xp[NNODES * 256];   // projected features, max H*C = 256
__device__ __align__(16) float g_h [NNODES * 64];    // hidden activations between layers
__device__ float g_as[NNODES * HEADS];
__device__ float g_ad[NNODES * HEADS];
__device__ int   g_cnt[NNODES];
__device__ int   g_cursor[NNODES];
__device__ int   g_rowstart[NNODES + 1];
__device__ int   g_esrc[E2MAX];

// ---------------- CSR build ----------------
__global__ void zero_counts_kernel() {
    int i = blockIdx.x * blockDim.x + threadIdx.x;
    if (i < NNODES) { g_cnt[i] = 0; g_cursor[i] = 0; }
}

// edge_index is int32 (JAX x64 disabled downcasts int64 -> int32)
__global__ void count_kernel(const int* __restrict__ ei, int E) {
    int e = blockIdx.x * blockDim.x + threadIdx.x;
    int e2 = E + NNODES;
    if (e >= e2) return;
    int dst = (e < E) ? ei[E + e] : (e - E);   // appended self-loops
    atomicAdd(&g_cnt[dst], 1);
}

__global__ void scan_kernel() {
    __shared__ int sm[1024];
    __shared__ int carry_s;
    int t = threadIdx.x;
    if (t == 0) carry_s = 0;
    __syncthreads();
    for (int base = 0; base < NNODES; base += 1024) {
        int i = base + t;
        int v = (i < NNODES) ? g_cnt[i] : 0;
        sm[t] = v;
        __syncthreads();
        #pragma unroll
        for (int off = 1; off < 1024; off <<= 1) {
            int tv = 0;
            if (t >= off) tv = sm[t - off];
            __syncthreads();
            if (t >= off) sm[t] += tv;
            __syncthreads();
        }
        int c0 = carry_s;
        if (i < NNODES) g_rowstart[i] = c0 + sm[t] - v;  // exclusive scan
        __syncthreads();
        if (t == 0) carry_s = c0 + sm[1023];
        __syncthreads();
    }
    if (t == 0) g_rowstart[NNODES] = carry_s;
}

__global__ void scatter_kernel(const int* __restrict__ ei, int E) {
    int e = blockIdx.x * blockDim.x + threadIdx.x;
    int e2 = E + NNODES;
    if (e >= e2) return;
    int src, dst;
    if (e < E) { src = ei[e]; dst = ei[E + e]; }
    else       { src = e - E; dst = src; }
    int pos = atomicAdd(&g_cursor[dst], 1);
    g_esrc[g_rowstart[dst] + pos] = src;
}

// ---------------- SGEMM: g_xp[M,Nc] = A[M,K] @ B[K,Nc], fp32 ----------------
// BM=128, BN=64, BK=16, thread tile 8x4, 256 threads
template<bool A_IS_GH>
__global__ __launch_bounds__(256) void sgemm_kernel(
    const float* __restrict__ A_ext, const float* __restrict__ B,
    int M, int Nc, int K)
{
    const float* __restrict__ A = A_IS_GH ? (const float*)g_h : A_ext;
    float* __restrict__ C = g_xp;

    const int BM = 128, BN = 64, BK = 16;
    __shared__ float As[BK][BM + 4];   // transposed A tile
    __shared__ float Bs[BK][BN];

    int tid = threadIdx.x;
    int m0 = blockIdx.y * BM, n0 = blockIdx.x * BN;
    int tx = tid & 15, ty = tid >> 4;

    float acc[8][4];
    #pragma unroll
    for (int i = 0; i < 8; i++)
        #pragma unroll
        for (int j = 0; j < 4; j++) acc[i][j] = 0.f;

    for (int k0 = 0; k0 < K; k0 += BK) {
        // load A tile 128x16 (2 x float4 per thread), transpose into As
        #pragma unroll
        for (int it = 0; it < 2; it++) {
            int r  = (tid >> 2) + it * 64;
            int cq = (tid & 3) * 4;
            float4 v = make_float4(0.f, 0.f, 0.f, 0.f);
            int gr = m0 + r;
            if (gr < M) v = *reinterpret_cast<const float4*>(A + (size_t)gr * K + (k0 + cq));
            As[cq + 0][r] = v.x; As[cq + 1][r] = v.y;
            As[cq + 2][r] = v.z; As[cq + 3][r] = v.w;
        }
        // load B tile 16x64 (1 x float4 per thread)
        {
            int kr = tid >> 4;
            int nq = (tid & 15) * 4;
            float4 v = make_float4(0.f, 0.f, 0.f, 0.f);
            int gc = n0 + nq;
            if (gc < Nc) v = *reinterpret_cast<const float4*>(B + (size_t)(k0 + kr) * Nc + gc);
            *reinterpret_cast<float4*>(&Bs[kr][nq]) = v;
        }
        __syncthreads();

        #pragma unroll
        for (int k = 0; k < BK; k++) {
            float a[8], b[4];
            float4 a0 = *reinterpret_cast<const float4*>(&As[k][ty * 8]);
            float4 a1 = *reinterpret_cast<const float4*>(&As[k][ty * 8 + 4]);
            a[0] = a0.x; a[1] = a0.y; a[2] = a0.z; a[3] = a0.w;
            a[4] = a1.x; a[5] = a1.y; a[6] = a1.z; a[7] = a1.w;
            float4 bv = *reinterpret_cast<const float4*>(&Bs[k][tx * 4]);
            b[0] = bv.x; b[1] = bv.y; b[2] = bv.z; b[3] = bv.w;
            #pragma unroll
            for (int i = 0; i < 8; i++)
                #pragma unroll
                for (int j = 0; j < 4; j++)
                    acc[i][j] = fmaf(a[i], b[j], acc[i][j]);
        }
        __syncthreads();
    }

    int gn = n0 + tx * 4;
    if (gn < Nc) {
        #pragma unroll
        for (int i = 0; i < 8; i++) {
            int gm = m0 + ty * 8 + i;
            if (gm < M) {
                *reinterpret_cast<float4*>(C + (size_t)gm * Nc + gn) =
                    make_float4(acc[i][0], acc[i][1], acc[i][2], acc[i][3]);
            }
        }
    }
}

// ---------------- alpha_s / alpha_d : per (node, head) dot products ----------------
// one warp per (node, head); reads g_xp, writes g_as / g_ad
__global__ void alpha_kernel(const float* __restrict__ a_s, const float* __restrict__ a_d,
                             int C)
{
    int gw = (blockIdx.x * blockDim.x + threadIdx.x) >> 5;
    if (gw >= NNODES * HEADS) return;
    int lane = threadIdx.x & 31;
    int n = gw >> 2, h = gw & 3;
    const float* row = g_xp + (size_t)n * HEADS * C + h * C;
    float ss = 0.f, sd = 0.f;
    for (int c = lane; c < C; c += 32) {
        float v = row[c];
        ss += v * a_s[h * C + c];
        sd += v * a_d[h * C + c];
    }
    #pragma unroll
    for (int o = 16; o; o >>= 1) {
        ss += __shfl_xor_sync(0xffffffffu, ss, o);
        sd += __shfl_xor_sync(0xffffffffu, sd, o);
    }
    if (lane == 0) {
        g_as[n * HEADS + h] = ss;
        g_ad[n * HEADS + h] = sd;
    }
}

// ---------------- aggregation: warp per dst node, online segment softmax ----------------
// lane -> (head h = lane>>3, slice sub = lane&7), EPL = C/8 accumulators/lane
template<int C, bool RELU, bool LOGSOFTMAX, bool OUT_IS_GH>
__global__ __launch_bounds__(256) void agg_kernel(
    const float* __restrict__ bias, float* __restrict__ out_ext)
{
    constexpr int EPL = C / 8;
    int warp = (blockIdx.x * blockDim.x + threadIdx.x) >> 5;
    if (warp >= NNODES) return;
    int lane = threadIdx.x & 31;
    int h = lane >> 3, sub = lane & 7;
    int n = warp;

    float adh = g_ad[n * HEADS + h];
    float m = __int_as_float(0xff800000);  // -inf
    float s = 0.f;
    float acc[EPL];
    #pragma unroll
    for (int k = 0; k < EPL; k++) acc[k] = 0.f;

    int beg = g_rowstart[n], end = g_rowstart[n + 1];
    for (int i = beg; i < end; i++) {
        int src = g_esrc[i];
        float e = g_as[src * HEADS + h] + adh;
        e = fmaxf(e, 0.2f * e);            // leaky_relu(0.2)
        float p;
        if (e > m) {
            float f = __expf(m - e);       // exp(-inf)=0 on the first edge
            s *= f;
            #pragma unroll
            for (int k = 0; k < EPL; k++) acc[k] *= f;
            m = e;
            p = 1.f;
        } else {
            p = __expf(e - m);
        }
        s += p;
        const float* row = g_xp + (size_t)src * (HEADS * C) + h * C + sub * EPL;
        if (EPL == 8) {
            float4 v0 = *reinterpret_cast<const float4*>(row);
            float4 v1 = *reinterpret_cast<const float4*>(row + 4);
            acc[0] = fmaf(p, v0.x, acc[0]); acc[1] = fmaf(p, v0.y, acc[1]);
            acc[2] = fmaf(p, v0.z, acc[2]); acc[3] = fmaf(p, v0.w, acc[3]);
            acc[4] = fmaf(p, v1.x, acc[4]); acc[5] = fmaf(p, v1.y, acc[5]);
            acc[6] = fmaf(p, v1.z, acc[6]); acc[7] = fmaf(p, v1.w, acc[7]);
        } else {
            #pragma unroll
            for (int k = 0; k < EPL; k++) acc[k] = fmaf(p, row[k], acc[k]);
        }
    }

    // per-head normalize, mean over heads (shfl across head groups), + bias
    float inv_s = 1.f / s;
    float r[EPL];
    #pragma unroll
    for (int k = 0; k < EPL; k++) {
        float v = acc[k] * inv_s;
        v += __shfl_xor_sync(0xffffffffu, v, 8);
        v += __shfl_xor_sync(0xffffffffu, v, 16);
        r[k] = 0.25f * v + bias[sub * EPL + k];
    }
    if (RELU) {
        #pragma unroll
        for (int k = 0; k < EPL; k++) r[k] = fmaxf(r[k], 0.f);
    }
    if (LOGSOFTMAX) {
        // values replicated across the 4 head groups; reduce over sub (xor 1,2,4)
        float lm = r[0];
        #pragma unroll
        for (int k = 1; k < EPL; k++) lm = fmaxf(lm, r[k]);
        #pragma unroll
        for (int o = 1; o < 8; o <<= 1) lm = fmaxf(lm, __shfl_xor_sync(0xffffffffu, lm, o));
        float le = 0.f;
        #pragma unroll
        for (int k = 0; k < EPL; k++) le += __expf(r[k] - lm);
        #pragma unroll
        for (int o = 1; o < 8; o <<= 1) le += __shfl_xor_sync(0xffffffffu, le, o);
        float lse = lm + __logf(le);
        #pragma unroll
        for (int k = 0; k < EPL; k++) r[k] -= lse;
    }
    if (h == 0) {
        float* op = (OUT_IS_GH ? (float*)g_h : out_ext) + (size_t)n * C + sub * EPL;
        #pragma unroll
        for (int k = 0; k < EPL; k++) op[k] = r[k];
    }
}

// ---------------- host orchestration ----------------
extern "C" void kernel_launch(void* const* d_in, const int* in_sizes, int n_in,
                              void* d_out, int out_size)
{
    const float* x   = (const float*)d_in[0];
    const int*   ei  = (const int*)d_in[1];      // int32 edge_index [2, E]
    const float* W1  = (const float*)d_in[2];
    const float* as1 = (const float*)d_in[3];
    const float* ad1 = (const float*)d_in[4];
    const float* b1  = (const float*)d_in[5];
    const float* W2  = (const float*)d_in[6];
    const float* as2 = (const float*)d_in[7];
    const float* ad2 = (const float*)d_in[8];
    const float* b2  = (const float*)d_in[9];
    const float* W3  = (const float*)d_in[10];
    const float* as3 = (const float*)d_in[11];
    const float* ad3 = (const float*)d_in[12];
    const float* b3  = (const float*)d_in[13];
    float* out = (float*)d_out;

    int E  = in_sizes[1] / 2;
    int e2 = E + NNODES;

    // CSR build (dst is shared by all 3 layers)
    zero_counts_kernel<<<(NNODES + 255) / 256, 256>>>();
    count_kernel<<<(e2 + 255) / 256, 256>>>(ei, E);
    scan_kernel<<<1, 1024>>>();
    scatter_kernel<<<(e2 + 255) / 256, 256>>>(ei, E);

    const int AGG_GRID   = (NNODES + 7) / 8;            // 8 warps / block
    const int ALPHA_GRID = (NNODES * HEADS + 7) / 8;    // 8 warps / block

    // ---- layer 1: IN=128 -> H*C=256 ----
    {
        dim3 grid((256 + 63) / 64, (NNODES + 127) / 128);
        sgemm_kernel<false><<<grid, 256>>>(x, W1, NNODES, 256, 128);
        alpha_kernel<<<ALPHA_GRID, 256>>>(as1, ad1, 64);
        agg_kernel<64, true, false, true><<<AGG_GRID, 256>>>(b1, out);
    }
    // ---- layer 2: 64 -> 256 ----
    {
        dim3 grid((256 + 63) / 64, (NNODES + 127) / 128);
        sgemm_kernel<true><<<grid, 256>>>(nullptr, W2, NNODES, 256, 64);
        alpha_kernel<<<ALPHA_GRID, 256>>>(as2, ad2, 64);
        agg_kernel<64, true, false, true><<<AGG_GRID, 256>>>(b2, out);
    }
    // ---- layer 3: 64 -> 160, fused relu + log_softmax ----
    {
        dim3 grid((160 + 63) / 64, (NNODES + 127) / 128);
        sgemm_kernel<true><<<grid, 256>>>(nullptr, W3, NNODES, 160, 64);
        alpha_kernel<<<ALPHA_GRID, 256>>>(as3, ad3, 40);
        agg_kernel<40, true, true, false><<<AGG_GRID, 256>>>(b3, out);
    }
}

// round 4
// speedup vs baseline: 1.1715x; 1.1715x over previous
#include <cuda_runtime.h>
#include <math.h>

#define NNODES 50000
#define EMAX   800000
#define E2MAX  (EMAX + NNODES)
#define HEADS  4

// ---------------- device scratch ----------------
__device__ __align__(16) float g_xp[NNODES * 256];
__device__ __align__(16) float g_h [NNODES * 64];
__device__ __align__(16) float g_as[NNODES * 4];
__device__ __align__(16) float g_ad[NNODES * 4];
__device__ unsigned g_gmax[12];                    // per-layer (3) x per-head (4) encoded max
__device__ int   g_cnt[NNODES];
__device__ int   g_cursor[NNODES];
__device__ int   g_rowstart[NNODES + 1];
__device__ int   g_esrc[E2MAX];
__device__ __align__(16) float g_bcat1[128 * 264];  // [W1 | W1@as1 | W1@ad1]
__device__ __align__(16) float g_bcat2[64  * 264];
__device__ __align__(16) float g_bcat3[64  * 168];

// order-preserving float <-> unsigned encoding (for atomicMax on floats)
__device__ __forceinline__ unsigned fenc(float f) {
    unsigned u = __float_as_uint(f);
    return (u & 0x80000000u) ? ~u : (u | 0x80000000u);
}
__device__ __forceinline__ float fdec(unsigned u) {
    u = (u & 0x80000000u) ? (u & 0x7fffffffu) : ~u;
    return __uint_as_float(u);
}

// ---------------- CSR build ----------------
__global__ void zero_counts_kernel() {
    int i = blockIdx.x * blockDim.x + threadIdx.x;
    if (i < NNODES) { g_cnt[i] = 0; g_cursor[i] = 0; }
    if (i < 12) g_gmax[i] = 0u;
}

__global__ void count_kernel(const int* __restrict__ ei, int E) {
    int e = blockIdx.x * blockDim.x + threadIdx.x;
    int e2 = E + NNODES;
    if (e >= e2) return;
    int dst = (e < E) ? ei[E + e] : (e - E);
    atomicAdd(&g_cnt[dst], 1);
}

#define SCHUNK ((NNODES + 1023) / 1024)
__global__ void scan_kernel() {
    __shared__ int wsum[32];
    int t = threadIdx.x;
    int lo = t * SCHUNK;
    int hi = min(lo + SCHUNK, NNODES);
    int sum = 0;
    for (int i = lo; i < hi; i++) sum += g_cnt[i];
    int lane = t & 31, w = t >> 5;
    int v = sum;
    #pragma unroll
    for (int o = 1; o < 32; o <<= 1) {
        int nv = __shfl_up_sync(0xffffffffu, v, o);
        if (lane >= o) v += nv;
    }
    if (lane == 31) wsum[w] = v;
    __syncthreads();
    if (w == 0) {
        int x = wsum[lane];
        #pragma unroll
        for (int o = 1; o < 32; o <<= 1) {
            int nv = __shfl_up_sync(0xffffffffu, x, o);
            if (lane >= o) x += nv;
        }
        wsum[lane] = x;
    }
    __syncthreads();
    int excl = v - sum + ((w > 0) ? wsum[w - 1] : 0);
    int run = excl;
    for (int i = lo; i < hi; i++) { g_rowstart[i] = run; run += g_cnt[i]; }
    if (hi == NNODES) g_rowstart[NNODES] = run;   // all writers agree on value
}

__global__ void scatter_kernel(const int* __restrict__ ei, int E) {
    int e = blockIdx.x * blockDim.x + threadIdx.x;
    int e2 = E + NNODES;
    if (e >= e2) return;
    int src, dst;
    if (e < E) { src = ei[e]; dst = ei[E + e]; }
    else       { src = e - E; dst = src; }
    int pos = atomicAdd(&g_cursor[dst], 1);
    g_esrc[g_rowstart[dst] + pos] = src;
}

// ---------------- Bcat = [W | W@a_s | W@a_d]  (weights-only, per layer) ----------------
template<int L>
__global__ void build_bcat_kernel(const float* __restrict__ W,
                                  const float* __restrict__ aw_s,
                                  const float* __restrict__ aw_d) {
    constexpr int K  = (L == 1) ? 128 : 64;
    constexpr int C  = (L == 3) ? 40 : 64;
    constexpr int HC = 4 * C;
    constexpr int Nc = HC + 8;
    float* bcat = (L == 1) ? g_bcat1 : (L == 2) ? g_bcat2 : g_bcat3;
    int idx = blockIdx.x * blockDim.x + threadIdx.x;
    if (idx >= K * Nc) return;
    int k = idx / Nc, j = idx - k * Nc;
    float v;
    if (j < HC) {
        v = W[k * HC + j];
    } else {
        int t = j - HC;
        int h = t & 3;
        const float* a = (t >= 4) ? aw_d : aw_s;
        float sum = 0.f;
        #pragma unroll 4
        for (int c = 0; c < C; c++) sum = fmaf(W[k * HC + h * C + c], a[h * C + c], sum);
        v = sum;
    }
    bcat[idx] = v;
}

// ---------------- SGEMM: [g_xp | g_as | g_ad] = A @ Bcat ----------------
// BM=128, BN=64, BK=16, thread tile 8x4, 256 threads
template<int L>
__global__ __launch_bounds__(256) void sgemm_kernel(const float* __restrict__ A_ext) {
    constexpr int K  = (L == 1) ? 128 : 64;
    constexpr int C  = (L == 3) ? 40 : 64;
    constexpr int HC = 4 * C;
    constexpr int Nc = HC + 8;
    constexpr int M  = NNODES;
    const float* __restrict__ A = (L == 1) ? A_ext : (const float*)g_h;
    const float* __restrict__ B = (L == 1) ? g_bcat1 : (L == 2) ? g_bcat2 : g_bcat3;

    const int BM = 128, BK = 16;
    __shared__ float As[BK][BM + 4];
    __shared__ float Bs[BK][64];

    int tid = threadIdx.x;
    int m0 = blockIdx.y * BM, n0 = blockIdx.x * 64;
    int tx = tid & 15, ty = tid >> 4;

    float acc[8][4];
    #pragma unroll
    for (int i = 0; i < 8; i++)
        #pragma unroll
        for (int j = 0; j < 4; j++) acc[i][j] = 0.f;

    for (int k0 = 0; k0 < K; k0 += BK) {
        #pragma unroll
        for (int it = 0; it < 2; it++) {
            int r  = (tid >> 2) + it * 64;
            int cq = (tid & 3) * 4;
            float4 v = make_float4(0.f, 0.f, 0.f, 0.f);
            int gr = m0 + r;
            if (gr < M) v = *reinterpret_cast<const float4*>(A + (size_t)gr * K + (k0 + cq));
            As[cq + 0][r] = v.x; As[cq + 1][r] = v.y;
            As[cq + 2][r] = v.z; As[cq + 3][r] = v.w;
        }
        {
            int kr = tid >> 4;
            int nq = (tid & 15) * 4;
            float4 v = make_float4(0.f, 0.f, 0.f, 0.f);
            int gc = n0 + nq;
            if (gc < Nc) v = *reinterpret_cast<const float4*>(B + (size_t)(k0 + kr) * Nc + gc);
            *reinterpret_cast<float4*>(&Bs[kr][nq]) = v;
        }
        __syncthreads();

        #pragma unroll
        for (int k = 0; k < BK; k++) {
            float a[8], b[4];
            float4 a0 = *reinterpret_cast<const float4*>(&As[k][ty * 8]);
            float4 a1 = *reinterpret_cast<const float4*>(&As[k][ty * 8 + 4]);
            a[0] = a0.x; a[1] = a0.y; a[2] = a0.z; a[3] = a0.w;
            a[4] = a1.x; a[5] = a1.y; a[6] = a1.z; a[7] = a1.w;
            float4 bv = *reinterpret_cast<const float4*>(&Bs[k][tx * 4]);
            b[0] = bv.x; b[1] = bv.y; b[2] = bv.z; b[3] = bv.w;
            #pragma unroll
            for (int i = 0; i < 8; i++)
                #pragma unroll
                for (int j = 0; j < 4; j++)
                    acc[i][j] = fmaf(a[i], b[j], acc[i][j]);
        }
        __syncthreads();
    }

    int gn = n0 + tx * 4;
    if (gn < Nc) {
        #pragma unroll
        for (int i = 0; i < 8; i++) {
            int gm = m0 + ty * 8 + i;
            if (gm < M) {
                float4 vv = make_float4(acc[i][0], acc[i][1], acc[i][2], acc[i][3]);
                if (gn < HC)
                    *reinterpret_cast<float4*>(g_xp + (size_t)gm * HC + gn) = vv;
                else if (gn == HC)
                    *reinterpret_cast<float4*>(g_as + gm * 4) = vv;
                else
                    *reinterpret_cast<float4*>(g_ad + gm * 4) = vv;
            }
        }
    }
}

// ---------------- per-head global max of g_as (softmax stabilizer bound) ----------------
__global__ void gmax_kernel(int base) {
    __shared__ unsigned sh[4];
    int t = threadIdx.x;
    if (t < 4) sh[t] = 0u;
    __syncthreads();
    int i = blockIdx.x * blockDim.x + t;
    unsigned v = 0u;
    if (i < NNODES * 4) v = fenc(g_as[i]);
    #pragma unroll
    for (int o = 4; o < 32; o <<= 1) v = max(v, __shfl_xor_sync(0xffffffffu, v, o));
    if ((t & 31) < 4) atomicMax(&sh[t & 3], v);
    __syncthreads();
    if (t < 4) atomicMax(&g_gmax[base + t], sh[t]);
}

// ---------------- aggregation: warp per dst node, fixed-stabilizer softmax ----------------
template<int L, bool RELU, bool LOGSM, bool OUT_GH>
__global__ __launch_bounds__(256) void agg_kernel(const float* __restrict__ bias,
                                                  float* __restrict__ out_ext) {
    constexpr int C   = (L == 3) ? 40 : 64;
    constexpr int HC  = 4 * C;
    constexpr int EPL = C / 8;
    int warp = (blockIdx.x * blockDim.x + threadIdx.x) >> 5;
    if (warp >= NNODES) return;
    int lane = threadIdx.x & 31;
    int h = lane >> 3, sub = lane & 7;
    int n = warp;

    float adh = g_ad[n * 4 + h];
    float Mh  = fdec(g_gmax[(L - 1) * 4 + h]);
    float em  = Mh + adh;
    float stab = fmaxf(em, 0.2f * em);   // >= every leaky(as_src + adh) in this segment

    float s = 0.f;
    float acc[EPL];
    #pragma unroll
    for (int k = 0; k < EPL; k++) acc[k] = 0.f;

    int beg = g_rowstart[n], end = g_rowstart[n + 1];
    int i = beg;
    for (; i + 1 < end; i += 2) {
        int s0 = g_esrc[i], s1 = g_esrc[i + 1];
        float e0 = g_as[s0 * 4 + h] + adh;
        float e1 = g_as[s1 * 4 + h] + adh;
        const float* r0 = g_xp + (size_t)s0 * HC + h * C + sub * EPL;
        const float* r1 = g_xp + (size_t)s1 * HC + h * C + sub * EPL;
        e0 = fmaxf(e0, 0.2f * e0);
        e1 = fmaxf(e1, 0.2f * e1);
        float p0 = __expf(e0 - stab);
        float p1 = __expf(e1 - stab);
        s += p0 + p1;
        if constexpr (EPL == 8) {
            float4 A0 = *reinterpret_cast<const float4*>(r0);
            float4 B0 = *reinterpret_cast<const float4*>(r0 + 4);
            float4 A1 = *reinterpret_cast<const float4*>(r1);
            float4 B1 = *reinterpret_cast<const float4*>(r1 + 4);
            acc[0] = fmaf(p0, A0.x, acc[0]); acc[1] = fmaf(p0, A0.y, acc[1]);
            acc[2] = fmaf(p0, A0.z, acc[2]); acc[3] = fmaf(p0, A0.w, acc[3]);
            acc[4] = fmaf(p0, B0.x, acc[4]); acc[5] = fmaf(p0, B0.y, acc[5]);
            acc[6] = fmaf(p0, B0.z, acc[6]); acc[7] = fmaf(p0, B0.w, acc[7]);
            acc[0] = fmaf(p1, A1.x, acc[0]); acc[1] = fmaf(p1, A1.y, acc[1]);
            acc[2] = fmaf(p1, A1.z, acc[2]); acc[3] = fmaf(p1, A1.w, acc[3]);
            acc[4] = fmaf(p1, B1.x, acc[4]); acc[5] = fmaf(p1, B1.y, acc[5]);
            acc[6] = fmaf(p1, B1.z, acc[6]); acc[7] = fmaf(p1, B1.w, acc[7]);
        } else {
            #pragma unroll
            for (int k = 0; k < EPL; k++) acc[k] = fmaf(p0, r0[k], acc[k]);
            #pragma unroll
            for (int k = 0; k < EPL; k++) acc[k] = fmaf(p1, r1[k], acc[k]);
        }
    }
    if (i < end) {
        int s0 = g_esrc[i];
        float e0 = g_as[s0 * 4 + h] + adh;
        e0 = fmaxf(e0, 0.2f * e0);
        float p0 = __expf(e0 - stab);
        s += p0;
        const float* r0 = g_xp + (size_t)s0 * HC + h * C + sub * EPL;
        if constexpr (EPL == 8) {
            float4 A0 = *reinterpret_cast<const float4*>(r0);
            float4 B0 = *reinterpret_cast<const float4*>(r0 + 4);
            acc[0] = fmaf(p0, A0.x, acc[0]); acc[1] = fmaf(p0, A0.y, acc[1]);
            acc[2] = fmaf(p0, A0.z, acc[2]); acc[3] = fmaf(p0, A0.w, acc[3]);
            acc[4] = fmaf(p0, B0.x, acc[4]); acc[5] = fmaf(p0, B0.y, acc[5]);
            acc[6] = fmaf(p0, B0.z, acc[6]); acc[7] = fmaf(p0, B0.w, acc[7]);
        } else {
            #pragma unroll
            for (int k = 0; k < EPL; k++) acc[k] = fmaf(p0, r0[k], acc[k]);
        }
    }

    // per-head normalize, mean over heads, + bias
    float inv_s = 1.f / s;
    float r[EPL];
    #pragma unroll
    for (int k = 0; k < EPL; k++) {
        float v = acc[k] * inv_s;
        v += __shfl_xor_sync(0xffffffffu, v, 8);
        v += __shfl_xor_sync(0xffffffffu, v, 16);
        r[k] = 0.25f * v + bias[sub * EPL + k];
    }
    if (RELU) {
        #pragma unroll
        for (int k = 0; k < EPL; k++) r[k] = fmaxf(r[k], 0.f);
    }
    if (LOGSM) {
        float lm = r[0];
        #pragma unroll
        for (int k = 1; k < EPL; k++) lm = fmaxf(lm, r[k]);
        #pragma unroll
        for (int o = 1; o < 8; o <<= 1) lm = fmaxf(lm, __shfl_xor_sync(0xffffffffu, lm, o));
        float le = 0.f;
        #pragma unroll
        for (int k = 0; k < EPL; k++) le += __expf(r[k] - lm);
        #pragma unroll
        for (int o = 1; o < 8; o <<= 1) le += __shfl_xor_sync(0xffffffffu, le, o);
        float lse = lm + __logf(le);
        #pragma unroll
        for (int k = 0; k < EPL; k++) r[k] -= lse;
    }
    if (h == 0) {
        float* op = (OUT_GH ? (float*)g_h : out_ext) + (size_t)n * C + sub * EPL;
        #pragma unroll
        for (int k = 0; k < EPL; k++) op[k] = r[k];
    }
}

// ---------------- host orchestration ----------------
extern "C" void kernel_launch(void* const* d_in, const int* in_sizes, int n_in,
                              void* d_out, int out_size)
{
    const float* x   = (const float*)d_in[0];
    const int*   ei  = (const int*)d_in[1];
    const float* W1  = (const float*)d_in[2];
    const float* as1 = (const float*)d_in[3];
    const float* ad1 = (const float*)d_in[4];
    const float* b1  = (const float*)d_in[5];
    const float* W2  = (const float*)d_in[6];
    const float* as2 = (const float*)d_in[7];
    const float* ad2 = (const float*)d_in[8];
    const float* b2  = (const float*)d_in[9];
    const float* W3  = (const float*)d_in[10];
    const float* as3 = (const float*)d_in[11];
    const float* ad3 = (const float*)d_in[12];
    const float* b3  = (const float*)d_in[13];
    float* out = (float*)d_out;

    int E  = in_sizes[1] / 2;
    int e2 = E + NNODES;

    // CSR (shared by all layers) + per-layer Bcat (weights only)
    zero_counts_kernel<<<(NNODES + 255) / 256, 256>>>();
    count_kernel<<<(e2 + 255) / 256, 256>>>(ei, E);
    scan_kernel<<<1, 1024>>>();
    scatter_kernel<<<(e2 + 255) / 256, 256>>>(ei, E);
    build_bcat_kernel<1><<<(128 * 264 + 255) / 256, 256>>>(W1, as1, ad1);
    build_bcat_kernel<2><<<(64  * 264 + 255) / 256, 256>>>(W2, as2, ad2);
    build_bcat_kernel<3><<<(64  * 168 + 255) / 256, 256>>>(W3, as3, ad3);

    const int AGG_GRID  = (NNODES + 7) / 8;
    const int GMAX_GRID = (NNODES * 4 + 255) / 256;
    const int MGRID     = (NNODES + 127) / 128;

    // layer 1: 128 -> 4x64 (+8 alpha cols)
    sgemm_kernel<1><<<dim3(5, MGRID), 256>>>(x);
    gmax_kernel<<<GMAX_GRID, 256>>>(0);
    agg_kernel<1, true, false, true><<<AGG_GRID, 256>>>(b1, out);

    // layer 2: 64 -> 4x64 (+8)
    sgemm_kernel<2><<<dim3(5, MGRID), 256>>>(nullptr);
    gmax_kernel<<<GMAX_GRID, 256>>>(4);
    agg_kernel<2, true, false, true><<<AGG_GRID, 256>>>(b2, out);

    // layer 3: 64 -> 4x40 (+8), fused relu + log_softmax
    sgemm_kernel<3><<<dim3(3, MGRID), 256>>>(nullptr);
    gmax_kernel<<<GMAX_GRID, 256>>>(8);
    agg_kernel<3, true, true, false><<<AGG_GRID, 256>>>(b3, out);
}

// round 5
// speedup vs baseline: 1.3149x; 1.1223x over previous
#include <cuda_runtime.h>
#include <cuda_fp16.h>
#include <math.h>

#define NNODES 50000
#define EMAX   800000
#define E2MAX  (EMAX + NNODES)
#define HEADS  4

// ---------------- device scratch ----------------
__device__ __align__(16) __half g_xph[NNODES * 256];  // fp16 projected features (layers 1/2)
__device__ __align__(16) float  g_xp [NNODES * 160];  // fp32 projected features (layer 3)
__device__ __align__(16) float  g_h  [NNODES * 64];   // fp32 activations between layers
__device__ __align__(16) float  g_as [NNODES * 4];
__device__ __align__(16) float  g_ad [NNODES * 4];
__device__ unsigned g_gmax[12];
__device__ int   g_cnt[NNODES];
__device__ int   g_cursor[NNODES];
__device__ int   g_rowstart[NNODES + 1];
__device__ int   g_esrc[E2MAX];
__device__ __align__(16) float g_bcat1[128 * 264];
__device__ __align__(16) float g_bcat2[64  * 264];
__device__ __align__(16) float g_bcat3[64  * 168];

__device__ __forceinline__ unsigned fenc(float f) {
    unsigned u = __float_as_uint(f);
    return (u & 0x80000000u) ? ~u : (u | 0x80000000u);
}
__device__ __forceinline__ float fdec(unsigned u) {
    u = (u & 0x80000000u) ? (u & 0x7fffffffu) : ~u;
    return __uint_as_float(u);
}

// ---------------- CSR build ----------------
__global__ void zero_counts_kernel() {
    int i = blockIdx.x * blockDim.x + threadIdx.x;
    if (i < NNODES) { g_cnt[i] = 0; g_cursor[i] = 0; }
    if (i < 12) g_gmax[i] = 0u;
}

__global__ void count_kernel(const int* __restrict__ ei, int E) {
    int e = blockIdx.x * blockDim.x + threadIdx.x;
    int e2 = E + NNODES;
    if (e >= e2) return;
    int dst = (e < E) ? ei[E + e] : (e - E);
    atomicAdd(&g_cnt[dst], 1);
}

#define SCHUNK ((NNODES + 1023) / 1024)
__global__ void scan_kernel() {
    __shared__ int wsum[32];
    int t = threadIdx.x;
    int lo = t * SCHUNK;
    int hi = min(lo + SCHUNK, NNODES);
    int sum = 0;
    for (int i = lo; i < hi; i++) sum += g_cnt[i];
    int lane = t & 31, w = t >> 5;
    int v = sum;
    #pragma unroll
    for (int o = 1; o < 32; o <<= 1) {
        int nv = __shfl_up_sync(0xffffffffu, v, o);
        if (lane >= o) v += nv;
    }
    if (lane == 31) wsum[w] = v;
    __syncthreads();
    if (w == 0) {
        int x = wsum[lane];
        #pragma unroll
        for (int o = 1; o < 32; o <<= 1) {
            int nv = __shfl_up_sync(0xffffffffu, x, o);
            if (lane >= o) x += nv;
        }
        wsum[lane] = x;
    }
    __syncthreads();
    int excl = v - sum + ((w > 0) ? wsum[w - 1] : 0);
    int run = excl;
    for (int i = lo; i < hi; i++) { g_rowstart[i] = run; run += g_cnt[i]; }
    if (hi == NNODES) g_rowstart[NNODES] = run;
}

__global__ void scatter_kernel(const int* __restrict__ ei, int E) {
    int e = blockIdx.x * blockDim.x + threadIdx.x;
    int e2 = E + NNODES;
    if (e >= e2) return;
    int src, dst;
    if (e < E) { src = ei[e]; dst = ei[E + e]; }
    else       { src = e - E; dst = src; }
    int pos = atomicAdd(&g_cursor[dst], 1);
    g_esrc[g_rowstart[dst] + pos] = src;
}

// ---------------- Bcat = [W | W@a_s | W@a_d] ----------------
template<int L>
__global__ void build_bcat_kernel(const float* __restrict__ W,
                                  const float* __restrict__ aw_s,
                                  const float* __restrict__ aw_d) {
    constexpr int K  = (L == 1) ? 128 : 64;
    constexpr int C  = (L == 3) ? 40 : 64;
    constexpr int HC = 4 * C;
    constexpr int Nc = HC + 8;
    float* bcat = (L == 1) ? g_bcat1 : (L == 2) ? g_bcat2 : g_bcat3;
    int idx = blockIdx.x * blockDim.x + threadIdx.x;
    if (idx >= K * Nc) return;
    int k = idx / Nc, j = idx - k * Nc;
    float v;
    if (j < HC) {
        v = W[k * HC + j];
    } else {
        int t = j - HC;
        int h = t & 3;
        const float* a = (t >= 4) ? aw_d : aw_s;
        float sum = 0.f;
        #pragma unroll 4
        for (int c = 0; c < C; c++) sum = fmaf(W[k * HC + h * C + c], a[h * C + c], sum);
        v = sum;
    }
    bcat[idx] = v;
}

// ---------------- SGEMM: [xp | g_as | g_ad] = A @ Bcat ----------------
// BM=128, BN=64, BK=16, thread tile 8x4, 256 threads
// Layers 1/2 write xp as fp16 (g_xph); layer 3 writes fp32 (g_xp).
template<int L>
__global__ __launch_bounds__(256) void sgemm_kernel(const float* __restrict__ A_ext) {
    constexpr int K  = (L == 1) ? 128 : 64;
    constexpr int C  = (L == 3) ? 40 : 64;
    constexpr int HC = 4 * C;
    constexpr int Nc = HC + 8;
    constexpr int M  = NNODES;
    const float* __restrict__ A = (L == 1) ? A_ext : (const float*)g_h;
    const float* __restrict__ B = (L == 1) ? g_bcat1 : (L == 2) ? g_bcat2 : g_bcat3;

    const int BM = 128, BK = 16;
    __shared__ float As[BK][BM + 4];
    __shared__ float Bs[BK][64];

    int tid = threadIdx.x;
    int m0 = blockIdx.y * BM, n0 = blockIdx.x * 64;
    int tx = tid & 15, ty = tid >> 4;

    float acc[8][4];
    #pragma unroll
    for (int i = 0; i < 8; i++)
        #pragma unroll
        for (int j = 0; j < 4; j++) acc[i][j] = 0.f;

    for (int k0 = 0; k0 < K; k0 += BK) {
        #pragma unroll
        for (int it = 0; it < 2; it++) {
            int r  = (tid >> 2) + it * 64;
            int cq = (tid & 3) * 4;
            float4 v = make_float4(0.f, 0.f, 0.f, 0.f);
            int gr = m0 + r;
            if (gr < M) v = *reinterpret_cast<const float4*>(A + (size_t)gr * K + (k0 + cq));
            As[cq + 0][r] = v.x; As[cq + 1][r] = v.y;
            As[cq + 2][r] = v.z; As[cq + 3][r] = v.w;
        }
        {
            int kr = tid >> 4;
            int nq = (tid & 15) * 4;
            float4 v = make_float4(0.f, 0.f, 0.f, 0.f);
            int gc = n0 + nq;
            if (gc < Nc) v = *reinterpret_cast<const float4*>(B + (size_t)(k0 + kr) * Nc + gc);
            *reinterpret_cast<float4*>(&Bs[kr][nq]) = v;
        }
        __syncthreads();

        #pragma unroll
        for (int k = 0; k < BK; k++) {
            float a[8], b[4];
            float4 a0 = *reinterpret_cast<const float4*>(&As[k][ty * 8]);
            float4 a1 = *reinterpret_cast<const float4*>(&As[k][ty * 8 + 4]);
            a[0] = a0.x; a[1] = a0.y; a[2] = a0.z; a[3] = a0.w;
            a[4] = a1.x; a[5] = a1.y; a[6] = a1.z; a[7] = a1.w;
            float4 bv = *reinterpret_cast<const float4*>(&Bs[k][tx * 4]);
            b[0] = bv.x; b[1] = bv.y; b[2] = bv.z; b[3] = bv.w;
            #pragma unroll
            for (int i = 0; i < 8; i++)
                #pragma unroll
                for (int j = 0; j < 4; j++)
                    acc[i][j] = fmaf(a[i], b[j], acc[i][j]);
        }
        __syncthreads();
    }

    int gn = n0 + tx * 4;
    if (gn < Nc) {
        #pragma unroll
        for (int i = 0; i < 8; i++) {
            int gm = m0 + ty * 8 + i;
            if (gm < M) {
                if (gn < HC) {
                    if constexpr (L == 3) {
                        *reinterpret_cast<float4*>(g_xp + (size_t)gm * HC + gn) =
                            make_float4(acc[i][0], acc[i][1], acc[i][2], acc[i][3]);
                    } else {
                        union { uint2 u; __half2 h[2]; } cv;
                        cv.h[0] = __floats2half2_rn(acc[i][0], acc[i][1]);
                        cv.h[1] = __floats2half2_rn(acc[i][2], acc[i][3]);
                        *reinterpret_cast<uint2*>(g_xph + (size_t)gm * HC + gn) = cv.u;
                    }
                } else if (gn == HC) {
                    *reinterpret_cast<float4*>(g_as + gm * 4) =
                        make_float4(acc[i][0], acc[i][1], acc[i][2], acc[i][3]);
                } else {
                    *reinterpret_cast<float4*>(g_ad + gm * 4) =
                        make_float4(acc[i][0], acc[i][1], acc[i][2], acc[i][3]);
                }
            }
        }
    }
}

// ---------------- per-head global max of g_as ----------------
__global__ void gmax_kernel(int base) {
    __shared__ unsigned sh[4];
    int t = threadIdx.x;
    if (t < 4) sh[t] = 0u;
    __syncthreads();
    int i = blockIdx.x * blockDim.x + t;
    unsigned v = 0u;
    if (i < NNODES * 4) v = fenc(g_as[i]);
    #pragma unroll
    for (int o = 4; o < 32; o <<= 1) v = max(v, __shfl_xor_sync(0xffffffffu, v, o));
    if ((t & 31) < 4) atomicMax(&sh[t & 3], v);
    __syncthreads();
    if (t < 4) atomicMax(&g_gmax[base + t], sh[t]);
}

// ---------------- aggregation: warp per dst node, fixed-stabilizer softmax ----------------
// Layers 1/2: fp16 features (one uint4 = 8 halves per lane per edge).
// Layer 3: fp32 features, EPL=5 scalar loads.
template<int L, bool RELU, bool LOGSM, bool OUT_GH>
__global__ __launch_bounds__(256) void agg_kernel(const float* __restrict__ bias,
                                                  float* __restrict__ out_ext) {
    constexpr int C   = (L == 3) ? 40 : 64;
    constexpr int HC  = 4 * C;
    constexpr int EPL = C / 8;
    int warp = (blockIdx.x * blockDim.x + threadIdx.x) >> 5;
    if (warp >= NNODES) return;
    int lane = threadIdx.x & 31;
    int h = lane >> 3, sub = lane & 7;
    int n = warp;

    float adh = g_ad[n * 4 + h];
    float Mh  = fdec(g_gmax[(L - 1) * 4 + h]);
    float em  = Mh + adh;
    float stab = fmaxf(em, 0.2f * em);

    float s = 0.f;
    float acc[EPL];
    #pragma unroll
    for (int k = 0; k < EPL; k++) acc[k] = 0.f;

    int beg = g_rowstart[n], end = g_rowstart[n + 1];

    #define FMA_HALF8(P, Q)                                                     \
        {                                                                       \
            float2 f0 = __half22float2(*reinterpret_cast<const __half2*>(&Q.x)); \
            float2 f1 = __half22float2(*reinterpret_cast<const __half2*>(&Q.y)); \
            float2 f2 = __half22float2(*reinterpret_cast<const __half2*>(&Q.z)); \
            float2 f3 = __half22float2(*reinterpret_cast<const __half2*>(&Q.w)); \
            acc[0] = fmaf(P, f0.x, acc[0]); acc[1] = fmaf(P, f0.y, acc[1]);     \
            acc[2] = fmaf(P, f1.x, acc[2]); acc[3] = fmaf(P, f1.y, acc[3]);     \
            acc[4] = fmaf(P, f2.x, acc[4]); acc[5] = fmaf(P, f2.y, acc[5]);     \
            acc[6] = fmaf(P, f3.x, acc[6]); acc[7] = fmaf(P, f3.y, acc[7]);     \
        }

    int i = beg;
    for (; i + 1 < end; i += 2) {
        int s0 = g_esrc[i], s1 = g_esrc[i + 1];
        float e0 = g_as[s0 * 4 + h] + adh;
        float e1 = g_as[s1 * 4 + h] + adh;
        e0 = fmaxf(e0, 0.2f * e0);
        e1 = fmaxf(e1, 0.2f * e1);
        float p0 = __expf(e0 - stab);
        float p1 = __expf(e1 - stab);
        s += p0 + p1;
        if constexpr (L != 3) {
            const __half* r0 = g_xph + (size_t)s0 * HC + h * 64 + sub * 8;
            const __half* r1 = g_xph + (size_t)s1 * HC + h * 64 + sub * 8;
            uint4 q0 = *reinterpret_cast<const uint4*>(r0);
            uint4 q1 = *reinterpret_cast<const uint4*>(r1);
            FMA_HALF8(p0, q0);
            FMA_HALF8(p1, q1);
        } else {
            const float* r0 = g_xp + (size_t)s0 * HC + h * C + sub * EPL;
            const float* r1 = g_xp + (size_t)s1 * HC + h * C + sub * EPL;
            #pragma unroll
            for (int k = 0; k < EPL; k++) acc[k] = fmaf(p0, r0[k], acc[k]);
            #pragma unroll
            for (int k = 0; k < EPL; k++) acc[k] = fmaf(p1, r1[k], acc[k]);
        }
    }
    if (i < end) {
        int s0 = g_esrc[i];
        float e0 = g_as[s0 * 4 + h] + adh;
        e0 = fmaxf(e0, 0.2f * e0);
        float p0 = __expf(e0 - stab);
        s += p0;
        if constexpr (L != 3) {
            const __half* r0 = g_xph + (size_t)s0 * HC + h * 64 + sub * 8;
            uint4 q0 = *reinterpret_cast<const uint4*>(r0);
            FMA_HALF8(p0, q0);
        } else {
            const float* r0 = g_xp + (size_t)s0 * HC + h * C + sub * EPL;
            #pragma unroll
            for (int k = 0; k < EPL; k++) acc[k] = fmaf(p0, r0[k], acc[k]);
        }
    }
    #undef FMA_HALF8

    float inv_s = 1.f / s;
    float r[EPL];
    #pragma unroll
    for (int k = 0; k < EPL; k++) {
        float v = acc[k] * inv_s;
        v += __shfl_xor_sync(0xffffffffu, v, 8);
        v += __shfl_xor_sync(0xffffffffu, v, 16);
        r[k] = 0.25f * v + bias[sub * EPL + k];
    }
    if (RELU) {
        #pragma unroll
        for (int k = 0; k < EPL; k++) r[k] = fmaxf(r[k], 0.f);
    }
    if (LOGSM) {
        float lm = r[0];
        #pragma unroll
        for (int k = 1; k < EPL; k++) lm = fmaxf(lm, r[k]);
        #pragma unroll
        for (int o = 1; o < 8; o <<= 1) lm = fmaxf(lm, __shfl_xor_sync(0xffffffffu, lm, o));
        float le = 0.f;
        #pragma unroll
        for (int k = 0; k < EPL; k++) le += __expf(r[k] - lm);
        #pragma unroll
        for (int o = 1; o < 8; o <<= 1) le += __shfl_xor_sync(0xffffffffu, le, o);
        float lse = lm + __logf(le);
        #pragma unroll
        for (int k = 0; k < EPL; k++) r[k] -= lse;
    }
    if (h == 0) {
        float* op = (OUT_GH ? (float*)g_h : out_ext) + (size_t)n * C + sub * EPL;
        #pragma unroll
        for (int k = 0; k < EPL; k++) op[k] = r[k];
    }
}

// ---------------- host orchestration ----------------
extern "C" void kernel_launch(void* const* d_in, const int* in_sizes, int n_in,
                              void* d_out, int out_size)
{
    const float* x   = (const float*)d_in[0];
    const int*   ei  = (const int*)d_in[1];
    const float* W1  = (const float*)d_in[2];
    const float* as1 = (const float*)d_in[3];
    const float* ad1 = (const float*)d_in[4];
    const float* b1  = (const float*)d_in[5];
    const float* W2  = (const float*)d_in[6];
    const float* as2 = (const float*)d_in[7];
    const float* ad2 = (const float*)d_in[8];
    const float* b2  = (const float*)d_in[9];
    const float* W3  = (const float*)d_in[10];
    const float* as3 = (const float*)d_in[11];
    const float* ad3 = (const float*)d_in[12];
    const float* b3  = (const float*)d_in[13];
    float* out = (float*)d_out;

    int E  = in_sizes[1] / 2;
    int e2 = E + NNODES;

    zero_counts_kernel<<<(NNODES + 255) / 256, 256>>>();
    count_kernel<<<(e2 + 255) / 256, 256>>>(ei, E);
    scan_kernel<<<1, 1024>>>();
    scatter_kernel<<<(e2 + 255) / 256, 256>>>(ei, E);
    build_bcat_kernel<1><<<(128 * 264 + 255) / 256, 256>>>(W1, as1, ad1);
    build_bcat_kernel<2><<<(64  * 264 + 255) / 256, 256>>>(W2, as2, ad2);
    build_bcat_kernel<3><<<(64  * 168 + 255) / 256, 256>>>(W3, as3, ad3);

    const int AGG_GRID  = (NNODES + 7) / 8;
    const int GMAX_GRID = (NNODES * 4 + 255) / 256;
    const int MGRID     = (NNODES + 127) / 128;

    sgemm_kernel<1><<<dim3(5, MGRID), 256>>>(x);
    gmax_kernel<<<GMAX_GRID, 256>>>(0);
    agg_kernel<1, true, false, true><<<AGG_GRID, 256>>>(b1, out);

    sgemm_kernel<2><<<dim3(5, MGRID), 256>>>(nullptr);
    gmax_kernel<<<GMAX_GRID, 256>>>(4);
    agg_kernel<2, true, false, true><<<AGG_GRID, 256>>>(b2, out);

    sgemm_kernel<3><<<dim3(3, MGRID), 256>>>(nullptr);
    gmax_kernel<<<GMAX_GRID, 256>>>(8);
    agg_kernel<3, true, true, false><<<AGG_GRID, 256>>>(b3, out);
}

// round 6
// speedup vs baseline: 1.7068x; 1.2981x over previous
#include <cuda_runtime.h>
#include <cuda_fp16.h>
#include <mma.h>
#include <math.h>

using namespace nvcuda;

#define NNODES 50000
#define EMAX   800000
#define E2MAX  (EMAX + NNODES)

// ---------------- device scratch ----------------
__device__ __align__(16) __half g_xph[NNODES * 256];  // fp16 projected features (L1/L2)
__device__ __align__(16) float  g_xp [NNODES * 160];  // fp32 projected features (L3)
__device__ __align__(16) __half g_xh [NNODES * 128];  // fp16 copy of input x
__device__ __align__(16) __half g_hh [NNODES * 64];   // fp16 hidden activations
__device__ __align__(16) float  g_as [NNODES * 4];
__device__ __align__(16) float  g_ad [NNODES * 4];
__device__ unsigned g_gmax[12];
__device__ int   g_cnt[NNODES];
__device__ int   g_cursor[NNODES];
__device__ int   g_rowstart[NNODES + 1];
__device__ int   g_esrc[E2MAX];
__device__ __align__(16) __half g_bcat1h[128 * 320];  // [W | W@a_s | W@a_d], zero-padded
__device__ __align__(16) __half g_bcat2h[64  * 320];
__device__ __align__(16) __half g_bcat3h[64  * 192];

__device__ __forceinline__ unsigned fenc(float f) {
    unsigned u = __float_as_uint(f);
    return (u & 0x80000000u) ? ~u : (u | 0x80000000u);
}
__device__ __forceinline__ float fdec(unsigned u) {
    u = (u & 0x80000000u) ? (u & 0x7fffffffu) : ~u;
    return __uint_as_float(u);
}

// ---------------- CSR build ----------------
__global__ void zero_counts_kernel() {
    int i = blockIdx.x * blockDim.x + threadIdx.x;
    if (i < NNODES) { g_cnt[i] = 0; g_cursor[i] = 0; }
    if (i < 12) g_gmax[i] = 0u;
}

__global__ void count_kernel(const int* __restrict__ ei, int E) {
    int e = blockIdx.x * blockDim.x + threadIdx.x;
    int e2 = E + NNODES;
    if (e >= e2) return;
    int dst = (e < E) ? ei[E + e] : (e - E);
    atomicAdd(&g_cnt[dst], 1);
}

#define SCHUNK ((NNODES + 1023) / 1024)
__global__ void scan_kernel() {
    __shared__ int wsum[32];
    int t = threadIdx.x;
    int lo = t * SCHUNK;
    int hi = min(lo + SCHUNK, NNODES);
    int sum = 0;
    for (int i = lo; i < hi; i++) sum += g_cnt[i];
    int lane = t & 31, w = t >> 5;
    int v = sum;
    #pragma unroll
    for (int o = 1; o < 32; o <<= 1) {
        int nv = __shfl_up_sync(0xffffffffu, v, o);
        if (lane >= o) v += nv;
    }
    if (lane == 31) wsum[w] = v;
    __syncthreads();
    if (w == 0) {
        int x = wsum[lane];
        #pragma unroll
        for (int o = 1; o < 32; o <<= 1) {
            int nv = __shfl_up_sync(0xffffffffu, x, o);
            if (lane >= o) x += nv;
        }
        wsum[lane] = x;
    }
    __syncthreads();
    int excl = v - sum + ((w > 0) ? wsum[w - 1] : 0);
    int run = excl;
    for (int i = lo; i < hi; i++) { g_rowstart[i] = run; run += g_cnt[i]; }
    if (hi == NNODES) g_rowstart[NNODES] = run;
}

__global__ void scatter_kernel(const int* __restrict__ ei, int E) {
    int e = blockIdx.x * blockDim.x + threadIdx.x;
    int e2 = E + NNODES;
    if (e >= e2) return;
    int src, dst;
    if (e < E) { src = ei[e]; dst = ei[E + e]; }
    else       { src = e - E; dst = src; }
    int pos = atomicAdd(&g_cursor[dst], 1);
    g_esrc[g_rowstart[dst] + pos] = src;
}

// ---------------- x -> fp16 ----------------
__global__ void convx_kernel(const float* __restrict__ x) {
    int i = blockIdx.x * blockDim.x + threadIdx.x;   // one per 8 elems
    if (i >= NNODES * 128 / 8) return;
    const float4* p = reinterpret_cast<const float4*>(x) + i * 2;
    float4 a = p[0], b = p[1];
    union { uint4 u; __half2 h[4]; } cv;
    cv.h[0] = __floats2half2_rn(a.x, a.y);
    cv.h[1] = __floats2half2_rn(a.z, a.w);
    cv.h[2] = __floats2half2_rn(b.x, b.y);
    cv.h[3] = __floats2half2_rn(b.z, b.w);
    *(reinterpret_cast<uint4*>(g_xh) + i) = cv.u;
}

// ---------------- Bcat = [W | W@a_s | W@a_d], fp16, zero-padded ----------------
template<int L>
__global__ void build_bcat_kernel(const float* __restrict__ W,
                                  const float* __restrict__ aw_s,
                                  const float* __restrict__ aw_d) {
    constexpr int K  = (L == 1) ? 128 : 64;
    constexpr int C  = (L == 3) ? 40 : 64;
    constexpr int HC = 4 * C;
    constexpr int Nc = HC + 8;
    constexpr int NP = (L == 3) ? 192 : 320;
    __half* bcat = (L == 1) ? g_bcat1h : (L == 2) ? g_bcat2h : g_bcat3h;
    int idx = blockIdx.x * blockDim.x + threadIdx.x;
    if (idx >= K * NP) return;
    int k = idx / NP, j = idx - k * NP;
    float v = 0.f;
    if (j < HC) {
        v = W[k * HC + j];
    } else if (j < Nc) {
        int t = j - HC;
        int h = t & 3;
        const float* a = (t >= 4) ? aw_d : aw_s;
        float sum = 0.f;
        #pragma unroll 4
        for (int c = 0; c < C; c++) sum = fmaf(W[k * HC + h * C + c], a[h * C + c], sum);
        v = sum;
    }
    bcat[idx] = __float2half_rn(v);
}

// ---------------- HGEMM (wmma, fp16 in / fp32 acc): [xp | g_as | g_ad] = A @ Bcat ----------------
// Block tile 128x64, BK=16, 8 warps (4x2), warp tile 32x32 = 2x2 wmma m16n16k16.
template<int L>
__global__ __launch_bounds__(256) void hgemm_kernel() {
    constexpr int K  = (L == 1) ? 128 : 64;
    constexpr int C  = (L == 3) ? 40 : 64;
    constexpr int HC = 4 * C;
    constexpr int NP = (L == 3) ? 192 : 320;
    constexpr int M  = NNODES;
    const __half* __restrict__ A = (L == 1) ? g_xh : g_hh;
    const __half* __restrict__ B = (L == 1) ? g_bcat1h : (L == 2) ? g_bcat2h : g_bcat3h;

    // smem: load stage (A 128x24, B 16x72 halves) aliased with epilogue C 128x68 floats
    __shared__ __align__(32) char smbuf[128 * 68 * 4];
    __half (*Ah)[24] = reinterpret_cast<__half(*)[24]>(smbuf);
    __half (*Bh)[72] = reinterpret_cast<__half(*)[72]>(smbuf + 128 * 24 * 2);
    float  (*Cs)[68] = reinterpret_cast<float(*)[68]>(smbuf);

    int tid  = threadIdx.x;
    int warp = tid >> 5, wm = warp >> 1, wn = warp & 1;
    int m0 = blockIdx.y * 128, n0 = blockIdx.x * 64;

    wmma::fragment<wmma::accumulator, 16, 16, 16, float> acc[2][2];
    #pragma unroll
    for (int i = 0; i < 2; i++)
        #pragma unroll
        for (int j = 0; j < 2; j++) wmma::fill_fragment(acc[i][j], 0.f);

    int ar = tid >> 1, acq = (tid & 1) * 8;
    int gm_a = m0 + ar;
    bool avalid = gm_a < M;
    const __half* aptr = A + (size_t)gm_a * K + acq;
    int bkr = tid >> 3, bnc = (tid & 7) * 8;
    const __half* bptr = B + (size_t)bkr * NP + n0 + bnc;

    for (int k0 = 0; k0 < K; k0 += 16) {
        uint4 va = make_uint4(0u, 0u, 0u, 0u);
        if (avalid) va = *reinterpret_cast<const uint4*>(aptr + k0);
        *reinterpret_cast<uint4*>(&Ah[ar][acq]) = va;
        if (tid < 128)
            *reinterpret_cast<uint4*>(&Bh[bkr][bnc]) =
                *reinterpret_cast<const uint4*>(bptr + (size_t)k0 * NP);
        __syncthreads();

        wmma::fragment<wmma::matrix_a, 16, 16, 16, __half, wmma::row_major> af;
        wmma::fragment<wmma::matrix_b, 16, 16, 16, __half, wmma::row_major> bf[2];
        #pragma unroll
        for (int j = 0; j < 2; j++)
            wmma::load_matrix_sync(bf[j], &Bh[0][wn * 32 + j * 16], 72);
        #pragma unroll
        for (int i = 0; i < 2; i++) {
            wmma::load_matrix_sync(af, &Ah[wm * 32 + i * 16][0], 24);
            #pragma unroll
            for (int j = 0; j < 2; j++)
                wmma::mma_sync(acc[i][j], af, bf[j], acc[i][j]);
        }
        __syncthreads();
    }

    // epilogue: stage fp32 accumulators in smem, then route columns
    #pragma unroll
    for (int i = 0; i < 2; i++)
        #pragma unroll
        for (int j = 0; j < 2; j++)
            wmma::store_matrix_sync(&Cs[wm * 32 + i * 16][wn * 32 + j * 16],
                                    acc[i][j], 68, wmma::mem_row_major);
    __syncthreads();

    #pragma unroll
    for (int pass = 0; pass < 4; pass++) {
        int row   = (tid >> 3) + pass * 32;
        int chunk = tid & 7;
        int gm = m0 + row;
        if (gm >= M) continue;
        int col0 = n0 + chunk * 8;
        float v[8];
        #pragma unroll
        for (int k = 0; k < 8; k++) v[k] = Cs[row][chunk * 8 + k];
        if (col0 < HC) {
            if constexpr (L == 3) {
                *reinterpret_cast<float4*>(g_xp + (size_t)gm * HC + col0) =
                    make_float4(v[0], v[1], v[2], v[3]);
                *reinterpret_cast<float4*>(g_xp + (size_t)gm * HC + col0 + 4) =
                    make_float4(v[4], v[5], v[6], v[7]);
            } else {
                union { uint4 u; __half2 h[4]; } cv;
                cv.h[0] = __floats2half2_rn(v[0], v[1]);
                cv.h[1] = __floats2half2_rn(v[2], v[3]);
                cv.h[2] = __floats2half2_rn(v[4], v[5]);
                cv.h[3] = __floats2half2_rn(v[6], v[7]);
                *reinterpret_cast<uint4*>(g_xph + (size_t)gm * HC + col0) = cv.u;
            }
        } else if (col0 == HC) {
            *reinterpret_cast<float4*>(g_as + gm * 4) = make_float4(v[0], v[1], v[2], v[3]);
            *reinterpret_cast<float4*>(g_ad + gm * 4) = make_float4(v[4], v[5], v[6], v[7]);
        }
    }
}

// ---------------- per-head global max of g_as ----------------
__global__ void gmax_kernel(int base) {
    __shared__ unsigned sh[4];
    int t = threadIdx.x;
    if (t < 4) sh[t] = 0u;
    __syncthreads();
    int i = blockIdx.x * blockDim.x + t;
    unsigned v = 0u;
    if (i < NNODES * 4) v = fenc(g_as[i]);
    #pragma unroll
    for (int o = 4; o < 32; o <<= 1) v = max(v, __shfl_xor_sync(0xffffffffu, v, o));
    if ((t & 31) < 4) atomicMax(&sh[t & 3], v);
    __syncthreads();
    if (t < 4) atomicMax(&g_gmax[base + t], sh[t]);
}

// ---------------- aggregation: warp per dst node, fixed-stabilizer softmax ----------------
template<int L, bool RELU, bool LOGSM, bool OUT_GH>
__global__ __launch_bounds__(256) void agg_kernel(const float* __restrict__ bias,
                                                  float* __restrict__ out_ext) {
    constexpr int C   = (L == 3) ? 40 : 64;
    constexpr int HC  = 4 * C;
    constexpr int EPL = C / 8;
    int warp = (blockIdx.x * blockDim.x + threadIdx.x) >> 5;
    if (warp >= NNODES) return;
    int lane = threadIdx.x & 31;
    int h = lane >> 3, sub = lane & 7;
    int n = warp;

    float adh = g_ad[n * 4 + h];
    float Mh  = fdec(g_gmax[(L - 1) * 4 + h]);
    float em  = Mh + adh;
    float stab = fmaxf(em, 0.2f * em);

    float s = 0.f;
    float acc[EPL];
    #pragma unroll
    for (int k = 0; k < EPL; k++) acc[k] = 0.f;

    int beg = g_rowstart[n], end = g_rowstart[n + 1];

    #define FMA_HALF8(P, Q)                                                      \
        {                                                                        \
            float2 f0 = __half22float2(*reinterpret_cast<const __half2*>(&Q.x)); \
            float2 f1 = __half22float2(*reinterpret_cast<const __half2*>(&Q.y)); \
            float2 f2 = __half22float2(*reinterpret_cast<const __half2*>(&Q.z)); \
            float2 f3 = __half22float2(*reinterpret_cast<const __half2*>(&Q.w)); \
            acc[0] = fmaf(P, f0.x, acc[0]); acc[1] = fmaf(P, f0.y, acc[1]);      \
            acc[2] = fmaf(P, f1.x, acc[2]); acc[3] = fmaf(P, f1.y, acc[3]);      \
            acc[4] = fmaf(P, f2.x, acc[4]); acc[5] = fmaf(P, f2.y, acc[5]);      \
            acc[6] = fmaf(P, f3.x, acc[6]); acc[7] = fmaf(P, f3.y, acc[7]);      \
        }

    int i = beg;
    for (; i + 1 < end; i += 2) {
        int s0 = g_esrc[i], s1 = g_esrc[i + 1];
        float e0 = g_as[s0 * 4 + h] + adh;
        float e1 = g_as[s1 * 4 + h] + adh;
        e0 = fmaxf(e0, 0.2f * e0);
        e1 = fmaxf(e1, 0.2f * e1);
        float p0 = __expf(e0 - stab);
        float p1 = __expf(e1 - stab);
        s += p0 + p1;
        if constexpr (L != 3) {
            const __half* r0 = g_xph + (size_t)s0 * HC + h * 64 + sub * 8;
            const __half* r1 = g_xph + (size_t)s1 * HC + h * 64 + sub * 8;
            uint4 q0 = *reinterpret_cast<const uint4*>(r0);
            uint4 q1 = *reinterpret_cast<const uint4*>(r1);
            FMA_HALF8(p0, q0);
            FMA_HALF8(p1, q1);
        } else {
            const float* r0 = g_xp + (size_t)s0 * HC + h * C + sub * EPL;
            const float* r1 = g_xp + (size_t)s1 * HC + h * C + sub * EPL;
            #pragma unroll
            for (int k = 0; k < EPL; k++) acc[k] = fmaf(p0, r0[k], acc[k]);
            #pragma unroll
            for (int k = 0; k < EPL; k++) acc[k] = fmaf(p1, r1[k], acc[k]);
        }
    }
    if (i < end) {
        int s0 = g_esrc[i];
        float e0 = g_as[s0 * 4 + h] + adh;
        e0 = fmaxf(e0, 0.2f * e0);
        float p0 = __expf(e0 - stab);
        s += p0;
        if constexpr (L != 3) {
            const __half* r0 = g_xph + (size_t)s0 * HC + h * 64 + sub * 8;
            uint4 q0 = *reinterpret_cast<const uint4*>(r0);
            FMA_HALF8(p0, q0);
        } else {
            const float* r0 = g_xp + (size_t)s0 * HC + h * C + sub * EPL;
            #pragma unroll
            for (int k = 0; k < EPL; k++) acc[k] = fmaf(p0, r0[k], acc[k]);
        }
    }
    #undef FMA_HALF8

    float inv_s = 1.f / s;
    float r[EPL];
    #pragma unroll
    for (int k = 0; k < EPL; k++) {
        float v = acc[k] * inv_s;
        v += __shfl_xor_sync(0xffffffffu, v, 8);
        v += __shfl_xor_sync(0xffffffffu, v, 16);
        r[k] = 0.25f * v + bias[sub * EPL + k];
    }
    if (RELU) {
        #pragma unroll
        for (int k = 0; k < EPL; k++) r[k] = fmaxf(r[k], 0.f);
    }
    if (LOGSM) {
        float lm = r[0];
        #pragma unroll
        for (int k = 1; k < EPL; k++) lm = fmaxf(lm, r[k]);
        #pragma unroll
        for (int o = 1; o < 8; o <<= 1) lm = fmaxf(lm, __shfl_xor_sync(0xffffffffu, lm, o));
        float le = 0.f;
        #pragma unroll
        for (int k = 0; k < EPL; k++) le += __expf(r[k] - lm);
        #pragma unroll
        for (int o = 1; o < 8; o <<= 1) le += __shfl_xor_sync(0xffffffffu, le, o);
        float lse = lm + __logf(le);
        #pragma unroll
        for (int k = 0; k < EPL; k++) r[k] -= lse;
    }
    if (h == 0) {
        if constexpr (OUT_GH) {
            // hidden activations stored fp16 for the next HGEMM
            union { uint4 u; __half2 h2[4]; } cv;
            cv.h2[0] = __floats2half2_rn(r[0], r[1]);
            cv.h2[1] = __floats2half2_rn(r[2], r[3]);
            cv.h2[2] = __floats2half2_rn(r[4], r[5]);
            cv.h2[3] = __floats2half2_rn(r[6], r[7]);
            *reinterpret_cast<uint4*>(g_hh + (size_t)n * 64 + sub * 8) = cv.u;
        } else {
            float* op = out_ext + (size_t)n * C + sub * EPL;
            #pragma unroll
            for (int k = 0; k < EPL; k++) op[k] = r[k];
        }
    }
}

// ---------------- host orchestration ----------------
extern "C" void kernel_launch(void* const* d_in, const int* in_sizes, int n_in,
                              void* d_out, int out_size)
{
    const float* x   = (const float*)d_in[0];
    const int*   ei  = (const int*)d_in[1];
    const float* W1  = (const float*)d_in[2];
    const float* as1 = (const float*)d_in[3];
    const float* ad1 = (const float*)d_in[4];
    const float* b1  = (const float*)d_in[5];
    const float* W2  = (const float*)d_in[6];
    const float* as2 = (const float*)d_in[7];
    const float* ad2 = (const float*)d_in[8];
    const float* b2  = (const float*)d_in[9];
    const float* W3  = (const float*)d_in[10];
    const float* as3 = (const float*)d_in[11];
    const float* ad3 = (const float*)d_in[12];
    const float* b3  = (const float*)d_in[13];
    float* out = (float*)d_out;

    int E  = in_sizes[1] / 2;
    int e2 = E + NNODES;

    zero_counts_kernel<<<(NNODES + 255) / 256, 256>>>();
    count_kernel<<<(e2 + 255) / 256, 256>>>(ei, E);
    scan_kernel<<<1, 1024>>>();
    scatter_kernel<<<(e2 + 255) / 256, 256>>>(ei, E);
    convx_kernel<<<(NNODES * 128 / 8 + 255) / 256, 256>>>(x);
    build_bcat_kernel<1><<<(128 * 320 + 255) / 256, 256>>>(W1, as1, ad1);
    build_bcat_kernel<2><<<(64  * 320 + 255) / 256, 256>>>(W2, as2, ad2);
    build_bcat_kernel<3><<<(64  * 192 + 255) / 256, 256>>>(W3, as3, ad3);

    const int AGG_GRID  = (NNODES + 7) / 8;
    const int GMAX_GRID = (NNODES * 4 + 255) / 256;
    const int MGRID     = (NNODES + 127) / 128;

    hgemm_kernel<1><<<dim3(5, MGRID), 256>>>();
    gmax_kernel<<<GMAX_GRID, 256>>>(0);
    agg_kernel<1, true, false, true><<<AGG_GRID, 256>>>(b1, out);

    hgemm_kernel<2><<<dim3(5, MGRID), 256>>>();
    gmax_kernel<<<GMAX_GRID, 256>>>(4);
    agg_kernel<2, true, false, true><<<AGG_GRID, 256>>>(b2, out);

    hgemm_kernel<3><<<dim3(3, MGRID), 256>>>();
    gmax_kernel<<<GMAX_GRID, 256>>>(8);
    agg_kernel<3, true, true, false><<<AGG_GRID, 256>>>(b3, out);
}